// round 4
// baseline (speedup 1.0000x reference)
#include <cuda_runtime.h>
#include <cstdint>
#include <cstddef>

#define D_MODEL   2048
#define D_STATE   128
#define D_CONV    4
#define D_SSM     4096
#define NHEADS    64
#define HEADDIM   64
#define CONV_DIM  (D_SSM + 2 * D_STATE)          // 4352
#define D_IN_PROJ (2 * D_SSM + 2 * D_STATE + NHEADS)  // 8512
#define BATCH     256

// Scratch (no allocations allowed)
__device__ float g_zxbcdt[BATCH * D_IN_PROJ];   // 8.7 MB
__device__ float g_xbc[BATCH * CONV_DIM];       // 4.5 MB
__device__ float g_y[BATCH * D_SSM];            // 4.2 MB

__device__ __forceinline__ uint32_t f2tf32(float f) {
    uint32_t u;
    asm("cvt.rna.tf32.f32 %0, %1;" : "=r"(u) : "f"(f));
    return u;
}

// ---------------------------------------------------------------------------
// GEMM: C[M,N] = A[M,K] @ B[N,K]^T (both K-major), tf32x3 split-precision MMA
// (near-fp32 accuracy). Tile: BM=64, BN=64, BK=32. 128 threads = 4 warps in
// 2x2, warp tile 32x32. Requires M%64==0, N%64==0, K%32==0. grid=(N/64, M/64).
// ---------------------------------------------------------------------------
__global__ __launch_bounds__(128) void gemm_tf32(
    const float* __restrict__ A, const float* __restrict__ B,
    float* __restrict__ C, int N, int K)
{
    __shared__ uint32_t AsH[64][33];
    __shared__ uint32_t AsL[64][33];
    __shared__ uint32_t BsH[64][33];
    __shared__ uint32_t BsL[64][33];

    const int tid  = threadIdx.x;
    const int warp = tid >> 5;
    const int lane = tid & 31;
    const int g    = lane >> 2;     // group id 0..7
    const int tg   = lane & 3;      // thread-in-group 0..3
    const int wr   = (warp >> 1) * 32;  // warp row offset within 64x64 tile
    const int wc   = (warp & 1) * 32;   // warp col offset
    const int m0   = blockIdx.y * 64;
    const int n0   = blockIdx.x * 64;

    float acc[2][4][4];
#pragma unroll
    for (int m = 0; m < 2; m++)
#pragma unroll
        for (int n = 0; n < 4; n++)
#pragma unroll
            for (int i = 0; i < 4; i++) acc[m][n][i] = 0.f;

    for (int kt = 0; kt < K; kt += 32) {
#pragma unroll
        for (int i = 0; i < 4; i++) {
            int f   = tid + i * 128;        // 0..511 (float4 index)
            int row = f >> 3;
            int c4  = (f & 7) << 2;
            float4 va = *reinterpret_cast<const float4*>(
                A + (size_t)(m0 + row) * K + kt + c4);
            float4 vb = *reinterpret_cast<const float4*>(
                B + (size_t)(n0 + row) * K + kt + c4);
            float av[4] = {va.x, va.y, va.z, va.w};
            float bv[4] = {vb.x, vb.y, vb.z, vb.w};
#pragma unroll
            for (int j = 0; j < 4; j++) {
                uint32_t ah = f2tf32(av[j]);
                AsH[row][c4 + j] = ah;
                AsL[row][c4 + j] = f2tf32(av[j] - __uint_as_float(ah));
                uint32_t bh = f2tf32(bv[j]);
                BsH[row][c4 + j] = bh;
                BsL[row][c4 + j] = f2tf32(bv[j] - __uint_as_float(bh));
            }
        }
        __syncthreads();

#pragma unroll
        for (int ks = 0; ks < 4; ks++) {
            const int k0 = ks * 8;
            uint32_t aH[2][4], aL[2][4], bH[4][2], bL[4][2];
#pragma unroll
            for (int m = 0; m < 2; m++) {
                int r = wr + m * 16 + g;
                aH[m][0] = AsH[r][k0 + tg];
                aH[m][1] = AsH[r + 8][k0 + tg];
                aH[m][2] = AsH[r][k0 + tg + 4];
                aH[m][3] = AsH[r + 8][k0 + tg + 4];
                aL[m][0] = AsL[r][k0 + tg];
                aL[m][1] = AsL[r + 8][k0 + tg];
                aL[m][2] = AsL[r][k0 + tg + 4];
                aL[m][3] = AsL[r + 8][k0 + tg + 4];
            }
#pragma unroll
            for (int n = 0; n < 4; n++) {
                int cc = wc + n * 8 + g;
                bH[n][0] = BsH[cc][k0 + tg];
                bH[n][1] = BsH[cc][k0 + tg + 4];
                bL[n][0] = BsL[cc][k0 + tg];
                bL[n][1] = BsL[cc][k0 + tg + 4];
            }
#define MMA(ar, br)                                                         \
    asm volatile(                                                           \
        "mma.sync.aligned.m16n8k8.row.col.f32.tf32.tf32.f32 "               \
        "{%0,%1,%2,%3}, {%4,%5,%6,%7}, {%8,%9}, {%0,%1,%2,%3};\n"           \
        : "+f"(acc[m][n][0]), "+f"(acc[m][n][1]),                           \
          "+f"(acc[m][n][2]), "+f"(acc[m][n][3])                            \
        : "r"(ar[m][0]), "r"(ar[m][1]), "r"(ar[m][2]), "r"(ar[m][3]),       \
          "r"(br[n][0]), "r"(br[n][1]))
#pragma unroll
            for (int m = 0; m < 2; m++)
#pragma unroll
                for (int n = 0; n < 4; n++) {
                    MMA(aL, bH);   // low-order terms first
                    MMA(aH, bL);
                    MMA(aH, bH);
                }
#undef MMA
        }
        __syncthreads();
    }

#pragma unroll
    for (int m = 0; m < 2; m++) {
        int r0 = m0 + wr + m * 16 + g;
#pragma unroll
        for (int n = 0; n < 4; n++) {
            int c0 = n0 + wc + n * 8 + tg * 2;
            C[(size_t)r0 * N + c0]           = acc[m][n][0];
            C[(size_t)r0 * N + c0 + 1]       = acc[m][n][1];
            C[(size_t)(r0 + 8) * N + c0]     = acc[m][n][2];
            C[(size_t)(r0 + 8) * N + c0 + 1] = acc[m][n][3];
        }
    }
}

// ---------------------------------------------------------------------------
// Conv state shift + depthwise conv + SiLU.
// One thread per (b, c). conv_state layout (B, CONV_DIM, 4) -> float4/thread.
// ---------------------------------------------------------------------------
__global__ void conv_kernel(
    const float* __restrict__ conv_state, const float* __restrict__ conv_w,
    const float* __restrict__ conv_b,
    float* __restrict__ conv_out, float* __restrict__ xbc_act)
{
    int idx = blockIdx.x * blockDim.x + threadIdx.x;  // b*CONV_DIM + c
    if (idx >= BATCH * CONV_DIM) return;
    int c = idx % CONV_DIM;
    int b = idx / CONV_DIM;

    float4 s = *reinterpret_cast<const float4*>(conv_state + (size_t)idx * 4);
    float4 w = *reinterpret_cast<const float4*>(conv_w + (size_t)c * 4);
    float xin = g_zxbcdt[(size_t)b * D_IN_PROJ + D_SSM + c];

    float4 ns = make_float4(s.y, s.z, s.w, xin);
    *reinterpret_cast<float4*>(conv_out + (size_t)idx * 4) = ns;

    float v = ns.x * w.x + ns.y * w.y + ns.z * w.z + ns.w * w.w + conv_b[c];
    xbc_act[idx] = v / (1.0f + expf(-v));
}

// ---------------------------------------------------------------------------
// SSM state update + y = (state_new @ C) + D*x, gated by SiLU(z).
// One block per (h, b). 4 warps; each warp handles 16 p-rows. Lane owns 4
// consecutive n (float4) -> fully coalesced 512B/row read+write of state.
// ---------------------------------------------------------------------------
__global__ __launch_bounds__(128) void state_kernel(
    const float* __restrict__ ssm_in, const float* __restrict__ dt_bias,
    const float* __restrict__ A_log, const float* __restrict__ Dp,
    float* __restrict__ ssm_out, float* __restrict__ y_out)
{
    const int h = blockIdx.x;
    const int b = blockIdx.y;
    const int warp = threadIdx.x >> 5;
    const int lane = threadIdx.x & 31;

    float dtraw = g_zxbcdt[(size_t)b * D_IN_PROJ + D_SSM + CONV_DIM + h] + dt_bias[h];
    // stable softplus: max(x,0) + log1p(exp(-|x|))
    float dt = fmaxf(dtraw, 0.f) + log1pf(expf(-fabsf(dtraw)));
    float A  = -expf(A_log[h]);
    float dA = expf(dt * A);
    float Dh = Dp[h];

    const float* xbc = g_xbc + (size_t)b * CONV_DIM;
    float4 B4 = *reinterpret_cast<const float4*>(xbc + D_SSM + lane * 4);
    float4 C4 = *reinterpret_cast<const float4*>(xbc + D_SSM + D_STATE + lane * 4);
    float4 dtB = make_float4(dt * B4.x, dt * B4.y, dt * B4.z, dt * B4.w);

    const size_t base = ((size_t)(b * NHEADS + h)) * HEADDIM * D_STATE;
    const float* zrow = g_zxbcdt + (size_t)b * D_IN_PROJ + h * HEADDIM;

#pragma unroll
    for (int i = 0; i < 16; i++) {
        int p = warp * 16 + i;
        float xp = xbc[h * HEADDIM + p];
        size_t off = base + (size_t)p * D_STATE + lane * 4;
        float4 s4 = *reinterpret_cast<const float4*>(ssm_in + off);
        float4 ns;
        ns.x = s4.x * dA + xp * dtB.x;
        ns.y = s4.y * dA + xp * dtB.y;
        ns.z = s4.z * dA + xp * dtB.z;
        ns.w = s4.w * dA + xp * dtB.w;
        *reinterpret_cast<float4*>(ssm_out + off) = ns;

        float yp = ns.x * C4.x + ns.y * C4.y + ns.z * C4.z + ns.w * C4.w;
#pragma unroll
        for (int o = 16; o > 0; o >>= 1)
            yp += __shfl_xor_sync(0xffffffff, yp, o);

        if (lane == 0) {
            float z  = zrow[p];
            float yv = yp + Dh * xp;
            y_out[(size_t)b * D_SSM + h * HEADDIM + p] =
                yv * (z / (1.f + expf(-z)));
        }
    }
}

// ---------------------------------------------------------------------------
extern "C" void kernel_launch(void* const* d_in, const int* in_sizes, int n_in,
                              void* d_out, int out_size)
{
    const float* hs         = (const float*)d_in[0];
    const float* conv_state = (const float*)d_in[1];
    const float* ssm_state  = (const float*)d_in[2];
    const float* in_proj_w  = (const float*)d_in[3];
    const float* conv_w     = (const float*)d_in[4];
    const float* conv_b     = (const float*)d_in[5];
    const float* dt_bias    = (const float*)d_in[6];
    const float* A_log      = (const float*)d_in[7];
    const float* Dp         = (const float*)d_in[8];
    const float* out_proj_w = (const float*)d_in[9];

    float* out      = (float*)d_out;
    float* conv_out = out + (size_t)BATCH * D_MODEL;
    float* ssm_out  = conv_out + (size_t)BATCH * CONV_DIM * D_CONV;

    float *zx, *xbc, *ybuf;
    cudaGetSymbolAddress((void**)&zx, g_zxbcdt);
    cudaGetSymbolAddress((void**)&xbc, g_xbc);
    cudaGetSymbolAddress((void**)&ybuf, g_y);

    // 1) zxbcdt = hs @ in_proj_w^T   (256 x 8512)
    gemm_tf32<<<dim3(D_IN_PROJ / 64, BATCH / 64), 128>>>(
        hs, in_proj_w, zx, D_IN_PROJ, D_MODEL);

    // 2) conv shift + conv + silu
    conv_kernel<<<(BATCH * CONV_DIM + 255) / 256, 256>>>(
        conv_state, conv_w, conv_b, conv_out, xbc);

    // 3) state update + gated y
    state_kernel<<<dim3(NHEADS, BATCH), 128>>>(
        ssm_state, dt_bias, A_log, Dp, ssm_out, ybuf);

    // 4) out = y @ out_proj_w^T   (256 x 2048)
    gemm_tf32<<<dim3(D_MODEL / 64, BATCH / 64), 128>>>(
        ybuf, out_proj_w, out, D_MODEL, D_SSM);
}

// round 7
// speedup vs baseline: 1.3360x; 1.3360x over previous
#include <cuda_runtime.h>
#include <cstdint>
#include <cstddef>

#define D_MODEL   2048
#define D_STATE   128
#define D_CONV    4
#define D_SSM     4096
#define NHEADS    64
#define HEADDIM   64
#define CONV_DIM  (D_SSM + 2 * D_STATE)          // 4352
#define D_IN_PROJ (2 * D_SSM + 2 * D_STATE + NHEADS)  // 8512
#define BATCH     256

#define SPLIT1 4   // GEMM1 K=2048 -> 4 x 512
#define SPLIT2 8   // GEMM2 K=4096 -> 8 x 512

// Scratch (no allocations allowed)
__device__ float g_zxbcdt[BATCH * D_IN_PROJ];           // 8.7 MB
__device__ float g_xbc[BATCH * CONV_DIM];               // 4.5 MB
__device__ float g_y[BATCH * D_SSM];                    // 4.2 MB
__device__ float g_part1[SPLIT1 * BATCH * D_IN_PROJ];   // 34.9 MB
__device__ float g_part2[SPLIT2 * BATCH * D_MODEL];     // 16.8 MB

__device__ __forceinline__ uint32_t f2tf32(float f) {
    uint32_t u;
    asm("cvt.rna.tf32.f32 %0, %1;" : "=r"(u) : "f"(f));
    return u;
}

// ---------------------------------------------------------------------------
// Split-K GEMM: Cpart[z] = A[:, z*Ks:(z+1)*Ks] @ B[:, z*Ks:(z+1)*Ks]^T
// A: [M,K] K-major, B: [N,K] K-major, tf32x3 split precision (near-fp32).
// Tile BM=64, BN=64, BK=32. 128 threads = 4 warps (2x2), warp tile 32x32.
// grid = (N/64, M/64, S).
// ---------------------------------------------------------------------------
__global__ __launch_bounds__(128) void gemm_tf32(
    const float* __restrict__ A, const float* __restrict__ B,
    float* __restrict__ Cpart, int N, int K, int Ksplit)
{
    __shared__ uint32_t AsH[64][33];
    __shared__ uint32_t AsL[64][33];
    __shared__ uint32_t BsH[64][33];
    __shared__ uint32_t BsL[64][33];

    const int tid  = threadIdx.x;
    const int warp = tid >> 5;
    const int lane = tid & 31;
    const int g    = lane >> 2;
    const int tg   = lane & 3;
    const int wr   = (warp >> 1) * 32;
    const int wc   = (warp & 1) * 32;
    const int m0   = blockIdx.y * 64;
    const int n0   = blockIdx.x * 64;
    const int kOff = blockIdx.z * Ksplit;
    const int M    = gridDim.y * 64;

    float acc[2][4][4];
#pragma unroll
    for (int m = 0; m < 2; m++)
#pragma unroll
        for (int n = 0; n < 4; n++)
#pragma unroll
            for (int i = 0; i < 4; i++) acc[m][n][i] = 0.f;

    for (int kt = kOff; kt < kOff + Ksplit; kt += 32) {
#pragma unroll
        for (int i = 0; i < 4; i++) {
            int f   = tid + i * 128;
            int row = f >> 3;
            int c4  = (f & 7) << 2;
            float4 va = *reinterpret_cast<const float4*>(
                A + (size_t)(m0 + row) * K + kt + c4);
            float4 vb = *reinterpret_cast<const float4*>(
                B + (size_t)(n0 + row) * K + kt + c4);
            float av[4] = {va.x, va.y, va.z, va.w};
            float bv[4] = {vb.x, vb.y, vb.z, vb.w};
#pragma unroll
            for (int j = 0; j < 4; j++) {
                uint32_t ah = f2tf32(av[j]);
                AsH[row][c4 + j] = ah;
                AsL[row][c4 + j] = f2tf32(av[j] - __uint_as_float(ah));
                uint32_t bh = f2tf32(bv[j]);
                BsH[row][c4 + j] = bh;
                BsL[row][c4 + j] = f2tf32(bv[j] - __uint_as_float(bh));
            }
        }
        __syncthreads();

#pragma unroll
        for (int ks = 0; ks < 4; ks++) {
            const int k0 = ks * 8;
            uint32_t aH[2][4], aL[2][4], bH[4][2], bL[4][2];
#pragma unroll
            for (int m = 0; m < 2; m++) {
                int r = wr + m * 16 + g;
                aH[m][0] = AsH[r][k0 + tg];
                aH[m][1] = AsH[r + 8][k0 + tg];
                aH[m][2] = AsH[r][k0 + tg + 4];
                aH[m][3] = AsH[r + 8][k0 + tg + 4];
                aL[m][0] = AsL[r][k0 + tg];
                aL[m][1] = AsL[r + 8][k0 + tg];
                aL[m][2] = AsL[r][k0 + tg + 4];
                aL[m][3] = AsL[r + 8][k0 + tg + 4];
            }
#pragma unroll
            for (int n = 0; n < 4; n++) {
                int cc = wc + n * 8 + g;
                bH[n][0] = BsH[cc][k0 + tg];
                bH[n][1] = BsH[cc][k0 + tg + 4];
                bL[n][0] = BsL[cc][k0 + tg];
                bL[n][1] = BsL[cc][k0 + tg + 4];
            }
#define MMA(ar, br)                                                         \
    asm volatile(                                                           \
        "mma.sync.aligned.m16n8k8.row.col.f32.tf32.tf32.f32 "               \
        "{%0,%1,%2,%3}, {%4,%5,%6,%7}, {%8,%9}, {%0,%1,%2,%3};\n"           \
        : "+f"(acc[m][n][0]), "+f"(acc[m][n][1]),                           \
          "+f"(acc[m][n][2]), "+f"(acc[m][n][3])                            \
        : "r"(ar[m][0]), "r"(ar[m][1]), "r"(ar[m][2]), "r"(ar[m][3]),       \
          "r"(br[n][0]), "r"(br[n][1]))
#pragma unroll
            for (int m = 0; m < 2; m++)
#pragma unroll
                for (int n = 0; n < 4; n++) {
                    MMA(aL, bH);   // low-order terms first
                    MMA(aH, bL);
                    MMA(aH, bH);
                }
#undef MMA
        }
        __syncthreads();
    }

    float* Cz = Cpart + (size_t)blockIdx.z * M * N;
#pragma unroll
    for (int m = 0; m < 2; m++) {
        int r0 = m0 + wr + m * 16 + g;
#pragma unroll
        for (int n = 0; n < 4; n++) {
            int c0 = n0 + wc + n * 8 + tg * 2;
            Cz[(size_t)r0 * N + c0]           = acc[m][n][0];
            Cz[(size_t)r0 * N + c0 + 1]       = acc[m][n][1];
            Cz[(size_t)(r0 + 8) * N + c0]     = acc[m][n][2];
            Cz[(size_t)(r0 + 8) * N + c0 + 1] = acc[m][n][3];
        }
    }
}

// ---------------------------------------------------------------------------
// Sum S split-K partials (float4 vectorized). n must be divisible by 4.
// ---------------------------------------------------------------------------
template <int S>
__global__ void reduce_k(const float* __restrict__ part,
                         float* __restrict__ out, int n4)
{
    int i = blockIdx.x * blockDim.x + threadIdx.x;
    if (i >= n4) return;
    const float4* p = reinterpret_cast<const float4*>(part);
    float4 a = p[i];
#pragma unroll
    for (int s = 1; s < S; s++) {
        float4 b = p[(size_t)s * n4 + i];
        a.x += b.x; a.y += b.y; a.z += b.z; a.w += b.w;
    }
    reinterpret_cast<float4*>(out)[i] = a;
}

// ---------------------------------------------------------------------------
// Conv state shift + depthwise conv + SiLU.
// ---------------------------------------------------------------------------
__global__ void conv_kernel(
    const float* __restrict__ conv_state, const float* __restrict__ conv_w,
    const float* __restrict__ conv_b,
    float* __restrict__ conv_out, float* __restrict__ xbc_act)
{
    int idx = blockIdx.x * blockDim.x + threadIdx.x;  // b*CONV_DIM + c
    if (idx >= BATCH * CONV_DIM) return;
    int c = idx % CONV_DIM;
    int b = idx / CONV_DIM;

    float4 s = *reinterpret_cast<const float4*>(conv_state + (size_t)idx * 4);
    float4 w = *reinterpret_cast<const float4*>(conv_w + (size_t)c * 4);
    float xin = g_zxbcdt[(size_t)b * D_IN_PROJ + D_SSM + c];

    float4 ns = make_float4(s.y, s.z, s.w, xin);
    *reinterpret_cast<float4*>(conv_out + (size_t)idx * 4) = ns;

    float v = ns.x * w.x + ns.y * w.y + ns.z * w.z + ns.w * w.w + conv_b[c];
    xbc_act[idx] = v / (1.0f + expf(-v));
}

// ---------------------------------------------------------------------------
// SSM state update + y = (state_new @ C) + D*x, gated by SiLU(z).
// One block per (h, b). 4 warps x 16 p-rows; lane owns 4 consecutive n.
// ---------------------------------------------------------------------------
__global__ __launch_bounds__(128) void state_kernel(
    const float* __restrict__ ssm_in, const float* __restrict__ dt_bias,
    const float* __restrict__ A_log, const float* __restrict__ Dp,
    float* __restrict__ ssm_out, float* __restrict__ y_out)
{
    const int h = blockIdx.x;
    const int b = blockIdx.y;
    const int warp = threadIdx.x >> 5;
    const int lane = threadIdx.x & 31;

    float dtraw = g_zxbcdt[(size_t)b * D_IN_PROJ + D_SSM + CONV_DIM + h] + dt_bias[h];
    float dt = fmaxf(dtraw, 0.f) + log1pf(expf(-fabsf(dtraw)));
    float A  = -expf(A_log[h]);
    float dA = expf(dt * A);
    float Dh = Dp[h];

    const float* xbc = g_xbc + (size_t)b * CONV_DIM;
    float4 B4 = *reinterpret_cast<const float4*>(xbc + D_SSM + lane * 4);
    float4 C4 = *reinterpret_cast<const float4*>(xbc + D_SSM + D_STATE + lane * 4);
    float4 dtB = make_float4(dt * B4.x, dt * B4.y, dt * B4.z, dt * B4.w);

    const size_t base = ((size_t)(b * NHEADS + h)) * HEADDIM * D_STATE;
    const float* zrow = g_zxbcdt + (size_t)b * D_IN_PROJ + h * HEADDIM;

#pragma unroll
    for (int i = 0; i < 16; i++) {
        int p = warp * 16 + i;
        float xp = xbc[h * HEADDIM + p];
        size_t off = base + (size_t)p * D_STATE + lane * 4;
        float4 s4 = *reinterpret_cast<const float4*>(ssm_in + off);
        float4 ns;
        ns.x = s4.x * dA + xp * dtB.x;
        ns.y = s4.y * dA + xp * dtB.y;
        ns.z = s4.z * dA + xp * dtB.z;
        ns.w = s4.w * dA + xp * dtB.w;
        *reinterpret_cast<float4*>(ssm_out + off) = ns;

        float yp = ns.x * C4.x + ns.y * C4.y + ns.z * C4.z + ns.w * C4.w;
#pragma unroll
        for (int o = 16; o > 0; o >>= 1)
            yp += __shfl_xor_sync(0xffffffff, yp, o);

        if (lane == 0) {
            float z  = zrow[p];
            float yv = yp + Dh * xp;
            y_out[(size_t)b * D_SSM + h * HEADDIM + p] =
                yv * (z / (1.f + expf(-z)));
        }
    }
}

// ---------------------------------------------------------------------------
extern "C" void kernel_launch(void* const* d_in, const int* in_sizes, int n_in,
                              void* d_out, int out_size)
{
    const float* hs         = (const float*)d_in[0];
    const float* conv_state = (const float*)d_in[1];
    const float* ssm_state  = (const float*)d_in[2];
    const float* in_proj_w  = (const float*)d_in[3];
    const float* conv_w     = (const float*)d_in[4];
    const float* conv_b     = (const float*)d_in[5];
    const float* dt_bias    = (const float*)d_in[6];
    const float* A_log      = (const float*)d_in[7];
    const float* Dp         = (const float*)d_in[8];
    const float* out_proj_w = (const float*)d_in[9];

    float* out      = (float*)d_out;
    float* conv_out = out + (size_t)BATCH * D_MODEL;
    float* ssm_out  = conv_out + (size_t)BATCH * CONV_DIM * D_CONV;

    float *zx, *xbc, *ybuf, *p1, *p2;
    cudaGetSymbolAddress((void**)&zx,  g_zxbcdt);
    cudaGetSymbolAddress((void**)&xbc, g_xbc);
    cudaGetSymbolAddress((void**)&ybuf, g_y);
    cudaGetSymbolAddress((void**)&p1,  g_part1);
    cudaGetSymbolAddress((void**)&p2,  g_part2);

    // 1) zxbcdt = hs @ in_proj_w^T   (256 x 8512), split-K x4
    gemm_tf32<<<dim3(D_IN_PROJ / 64, BATCH / 64, SPLIT1), 128>>>(
        hs, in_proj_w, p1, D_IN_PROJ, D_MODEL, D_MODEL / SPLIT1);
    {
        int n4 = BATCH * D_IN_PROJ / 4;
        reduce_k<SPLIT1><<<(n4 + 255) / 256, 256>>>(p1, zx, n4);
    }

    // 2) conv shift + conv + silu
    conv_kernel<<<(BATCH * CONV_DIM + 255) / 256, 256>>>(
        conv_state, conv_w, conv_b, conv_out, xbc);

    // 3) state update + gated y
    state_kernel<<<dim3(NHEADS, BATCH), 128>>>(
        ssm_state, dt_bias, A_log, Dp, ssm_out, ybuf);

    // 4) out = y @ out_proj_w^T   (256 x 2048), split-K x8
    gemm_tf32<<<dim3(D_MODEL / 64, BATCH / 64, SPLIT2), 128>>>(
        ybuf, out_proj_w, p2, D_MODEL, D_SSM, D_SSM / SPLIT2);
    {
        int n4 = BATCH * D_MODEL / 4;
        reduce_k<SPLIT2><<<(n4 + 255) / 256, 256>>>(p2, out, n4);
    }
}

// round 8
// speedup vs baseline: 1.8408x; 1.3779x over previous
#include <cuda_runtime.h>
#include <cstdint>
#include <cstddef>

#define D_MODEL   2048
#define D_STATE   128
#define D_CONV    4
#define D_SSM     4096
#define NHEADS    64
#define HEADDIM   64
#define CONV_DIM  (D_SSM + 2 * D_STATE)          // 4352
#define D_IN_PROJ (2 * D_SSM + 2 * D_STATE + NHEADS)  // 8512
#define BATCH     256

#define SPLIT1 4   // GEMM1 K=2048 -> 4 x 512
#define SPLIT2 8   // GEMM2 K=4096 -> 8 x 512

// Scratch (no allocations allowed)
__device__ float g_zxbcdt[BATCH * D_IN_PROJ];           // 8.7 MB
__device__ float g_xbc[BATCH * CONV_DIM];               // 4.5 MB
__device__ float g_y[BATCH * D_SSM];                    // 4.2 MB
__device__ float g_part1[SPLIT1 * BATCH * D_IN_PROJ];   // 34.9 MB
__device__ float g_part2[SPLIT2 * BATCH * D_MODEL];     // 16.8 MB

__device__ __forceinline__ uint32_t f2tf32(float f) {
    uint32_t u;
    asm("cvt.rna.tf32.f32 %0, %1;" : "=r"(u) : "f"(f));
    return u;
}

__device__ __forceinline__ void cp16(uint32_t smem_addr, const float* gptr) {
    asm volatile("cp.async.cg.shared.global [%0], [%1], 16;\n"
                 :: "r"(smem_addr), "l"(gptr));
}

// ---------------------------------------------------------------------------
// Split-K GEMM: Cpart[z] = A[:, z*Ks:(z+1)*Ks] @ B[:, z*Ks:(z+1)*Ks]^T
// A: [M,K] K-major, B: [N,K] K-major, tf32x3 split precision (near-fp32).
// Raw fp32 staged in smem via cp.async 2-stage pipeline; H/L tf32 split done
// in registers at fragment-load time. Tile BM=64, BN=64, BK=32; 128 threads.
// grid = (N/64, M/64, S).
// ---------------------------------------------------------------------------
__global__ __launch_bounds__(128) void gemm_tf32(
    const float* __restrict__ A, const float* __restrict__ B,
    float* __restrict__ Cpart, int N, int K, int Ksplit)
{
    // stride 36 floats: 144B rows (16B-aligned for cp.async), and the
    // fragment access pattern (4r+tg) is bank-conflict-free.
    __shared__ float As[2][64][36];
    __shared__ float Bs[2][64][36];

    const int tid  = threadIdx.x;
    const int warp = tid >> 5;
    const int lane = tid & 31;
    const int g    = lane >> 2;
    const int tg   = lane & 3;
    const int wr   = (warp >> 1) * 32;
    const int wc   = (warp & 1) * 32;
    const int m0   = blockIdx.y * 64;
    const int n0   = blockIdx.x * 64;
    const int kOff = blockIdx.z * Ksplit;
    const int M    = gridDim.y * 64;
    const int nT   = Ksplit / 32;

    // copy mapping: each thread moves 4 float4 per matrix per tile
    const int crow = tid >> 1;            // 0..63 (two threads per row)
    const int cc0  = (tid & 1) * 16;      // float offset 0 or 16

    float acc[2][4][4];
#pragma unroll
    for (int m = 0; m < 2; m++)
#pragma unroll
        for (int n = 0; n < 4; n++)
#pragma unroll
            for (int i = 0; i < 4; i++) acc[m][n][i] = 0.f;

    // ---- async copy of one 64x32 tile pair into buffer `buf` ----
    auto copy_tile = [&](int buf, int kt) {
        const float* ga = A + (size_t)(m0 + crow) * K + kt + cc0;
        const float* gb = B + (size_t)(n0 + crow) * K + kt + cc0;
        uint32_t sa = (uint32_t)__cvta_generic_to_shared(&As[buf][crow][cc0]);
        uint32_t sb = (uint32_t)__cvta_generic_to_shared(&Bs[buf][crow][cc0]);
#pragma unroll
        for (int j = 0; j < 4; j++) {
            cp16(sa + j * 16, ga + j * 4);
            cp16(sb + j * 16, gb + j * 4);
        }
    };

    copy_tile(0, kOff);
    asm volatile("cp.async.commit_group;\n" ::: "memory");

    for (int t = 0; t < nT; t++) {
        const int buf = t & 1;
        if (t + 1 < nT) {
            copy_tile(buf ^ 1, kOff + (t + 1) * 32);
            asm volatile("cp.async.commit_group;\n" ::: "memory");
            asm volatile("cp.async.wait_group 1;\n" ::: "memory");
        } else {
            asm volatile("cp.async.wait_group 0;\n" ::: "memory");
        }
        __syncthreads();

#pragma unroll
        for (int ks = 0; ks < 4; ks++) {
            const int k0 = ks * 8;
            float ar[2][4], br[4][2];
#pragma unroll
            for (int m = 0; m < 2; m++) {
                int r = wr + m * 16 + g;
                ar[m][0] = As[buf][r][k0 + tg];
                ar[m][1] = As[buf][r + 8][k0 + tg];
                ar[m][2] = As[buf][r][k0 + tg + 4];
                ar[m][3] = As[buf][r + 8][k0 + tg + 4];
            }
#pragma unroll
            for (int n = 0; n < 4; n++) {
                int cc = wc + n * 8 + g;
                br[n][0] = Bs[buf][cc][k0 + tg];
                br[n][1] = Bs[buf][cc][k0 + tg + 4];
            }
            // register-side tf32 H/L split
            uint32_t aH[2][4], aL[2][4], bH[4][2], bL[4][2];
#pragma unroll
            for (int m = 0; m < 2; m++)
#pragma unroll
                for (int i = 0; i < 4; i++) {
                    uint32_t h = f2tf32(ar[m][i]);
                    aH[m][i] = h;
                    aL[m][i] = f2tf32(ar[m][i] - __uint_as_float(h));
                }
#pragma unroll
            for (int n = 0; n < 4; n++)
#pragma unroll
                for (int i = 0; i < 2; i++) {
                    uint32_t h = f2tf32(br[n][i]);
                    bH[n][i] = h;
                    bL[n][i] = f2tf32(br[n][i] - __uint_as_float(h));
                }
#define MMA(ar_, br_)                                                       \
    asm volatile(                                                           \
        "mma.sync.aligned.m16n8k8.row.col.f32.tf32.tf32.f32 "               \
        "{%0,%1,%2,%3}, {%4,%5,%6,%7}, {%8,%9}, {%0,%1,%2,%3};\n"           \
        : "+f"(acc[m][n][0]), "+f"(acc[m][n][1]),                           \
          "+f"(acc[m][n][2]), "+f"(acc[m][n][3])                            \
        : "r"(ar_[m][0]), "r"(ar_[m][1]), "r"(ar_[m][2]), "r"(ar_[m][3]),   \
          "r"(br_[n][0]), "r"(br_[n][1]))
#pragma unroll
            for (int m = 0; m < 2; m++)
#pragma unroll
                for (int n = 0; n < 4; n++) {
                    MMA(aL, bH);   // low-order terms first
                    MMA(aH, bL);
                    MMA(aH, bH);
                }
#undef MMA
        }
        __syncthreads();
    }

    float* Cz = Cpart + (size_t)blockIdx.z * M * N;
#pragma unroll
    for (int m = 0; m < 2; m++) {
        int r0 = m0 + wr + m * 16 + g;
#pragma unroll
        for (int n = 0; n < 4; n++) {
            int c0 = n0 + wc + n * 8 + tg * 2;
            Cz[(size_t)r0 * N + c0]           = acc[m][n][0];
            Cz[(size_t)r0 * N + c0 + 1]       = acc[m][n][1];
            Cz[(size_t)(r0 + 8) * N + c0]     = acc[m][n][2];
            Cz[(size_t)(r0 + 8) * N + c0 + 1] = acc[m][n][3];
        }
    }
}

// ---------------------------------------------------------------------------
// Sum S split-K partials (float4 vectorized).
// ---------------------------------------------------------------------------
template <int S>
__global__ void reduce_k(const float* __restrict__ part,
                         float* __restrict__ out, int n4)
{
    int i = blockIdx.x * blockDim.x + threadIdx.x;
    if (i >= n4) return;
    const float4* p = reinterpret_cast<const float4*>(part);
    float4 a = p[i];
#pragma unroll
    for (int s = 1; s < S; s++) {
        float4 b = p[(size_t)s * n4 + i];
        a.x += b.x; a.y += b.y; a.z += b.z; a.w += b.w;
    }
    reinterpret_cast<float4*>(out)[i] = a;
}

// ---------------------------------------------------------------------------
// Conv state shift + depthwise conv + SiLU.
// ---------------------------------------------------------------------------
__global__ void conv_kernel(
    const float* __restrict__ conv_state, const float* __restrict__ conv_w,
    const float* __restrict__ conv_b,
    float* __restrict__ conv_out, float* __restrict__ xbc_act)
{
    int idx = blockIdx.x * blockDim.x + threadIdx.x;  // b*CONV_DIM + c
    if (idx >= BATCH * CONV_DIM) return;
    int c = idx % CONV_DIM;
    int b = idx / CONV_DIM;

    float4 s = *reinterpret_cast<const float4*>(conv_state + (size_t)idx * 4);
    float4 w = *reinterpret_cast<const float4*>(conv_w + (size_t)c * 4);
    float xin = g_zxbcdt[(size_t)b * D_IN_PROJ + D_SSM + c];

    float4 ns = make_float4(s.y, s.z, s.w, xin);
    *reinterpret_cast<float4*>(conv_out + (size_t)idx * 4) = ns;

    float v = ns.x * w.x + ns.y * w.y + ns.z * w.z + ns.w * w.w + conv_b[c];
    xbc_act[idx] = v / (1.0f + expf(-v));
}

// ---------------------------------------------------------------------------
// SSM state update + y = (state_new @ C) + D*x, gated by SiLU(z).
// One block per (h, b). 4 warps x 16 p-rows; lane owns 4 consecutive n.
// ---------------------------------------------------------------------------
__global__ __launch_bounds__(128) void state_kernel(
    const float* __restrict__ ssm_in, const float* __restrict__ dt_bias,
    const float* __restrict__ A_log, const float* __restrict__ Dp,
    float* __restrict__ ssm_out, float* __restrict__ y_out)
{
    const int h = blockIdx.x;
    const int b = blockIdx.y;
    const int warp = threadIdx.x >> 5;
    const int lane = threadIdx.x & 31;

    float dtraw = g_zxbcdt[(size_t)b * D_IN_PROJ + D_SSM + CONV_DIM + h] + dt_bias[h];
    float dt = fmaxf(dtraw, 0.f) + log1pf(expf(-fabsf(dtraw)));
    float A  = -expf(A_log[h]);
    float dA = expf(dt * A);
    float Dh = Dp[h];

    const float* xbc = g_xbc + (size_t)b * CONV_DIM;
    float4 B4 = *reinterpret_cast<const float4*>(xbc + D_SSM + lane * 4);
    float4 C4 = *reinterpret_cast<const float4*>(xbc + D_SSM + D_STATE + lane * 4);
    float4 dtB = make_float4(dt * B4.x, dt * B4.y, dt * B4.z, dt * B4.w);

    const size_t base = ((size_t)(b * NHEADS + h)) * HEADDIM * D_STATE;
    const float* zrow = g_zxbcdt + (size_t)b * D_IN_PROJ + h * HEADDIM;

#pragma unroll
    for (int i = 0; i < 16; i++) {
        int p = warp * 16 + i;
        float xp = xbc[h * HEADDIM + p];
        size_t off = base + (size_t)p * D_STATE + lane * 4;
        float4 s4 = *reinterpret_cast<const float4*>(ssm_in + off);
        float4 ns;
        ns.x = s4.x * dA + xp * dtB.x;
        ns.y = s4.y * dA + xp * dtB.y;
        ns.z = s4.z * dA + xp * dtB.z;
        ns.w = s4.w * dA + xp * dtB.w;
        *reinterpret_cast<float4*>(ssm_out + off) = ns;

        float yp = ns.x * C4.x + ns.y * C4.y + ns.z * C4.z + ns.w * C4.w;
#pragma unroll
        for (int o = 16; o > 0; o >>= 1)
            yp += __shfl_xor_sync(0xffffffff, yp, o);

        if (lane == 0) {
            float z  = zrow[p];
            float yv = yp + Dh * xp;
            y_out[(size_t)b * D_SSM + h * HEADDIM + p] =
                yv * (z / (1.f + expf(-z)));
        }
    }
}

// ---------------------------------------------------------------------------
extern "C" void kernel_launch(void* const* d_in, const int* in_sizes, int n_in,
                              void* d_out, int out_size)
{
    const float* hs         = (const float*)d_in[0];
    const float* conv_state = (const float*)d_in[1];
    const float* ssm_state  = (const float*)d_in[2];
    const float* in_proj_w  = (const float*)d_in[3];
    const float* conv_w     = (const float*)d_in[4];
    const float* conv_b     = (const float*)d_in[5];
    const float* dt_bias    = (const float*)d_in[6];
    const float* A_log      = (const float*)d_in[7];
    const float* Dp         = (const float*)d_in[8];
    const float* out_proj_w = (const float*)d_in[9];

    float* out      = (float*)d_out;
    float* conv_out = out + (size_t)BATCH * D_MODEL;
    float* ssm_out  = conv_out + (size_t)BATCH * CONV_DIM * D_CONV;

    float *zx, *xbc, *ybuf, *p1, *p2;
    cudaGetSymbolAddress((void**)&zx,  g_zxbcdt);
    cudaGetSymbolAddress((void**)&xbc, g_xbc);
    cudaGetSymbolAddress((void**)&ybuf, g_y);
    cudaGetSymbolAddress((void**)&p1,  g_part1);
    cudaGetSymbolAddress((void**)&p2,  g_part2);

    // 1) zxbcdt = hs @ in_proj_w^T   (256 x 8512), split-K x4
    gemm_tf32<<<dim3(D_IN_PROJ / 64, BATCH / 64, SPLIT1), 128>>>(
        hs, in_proj_w, p1, D_IN_PROJ, D_MODEL, D_MODEL / SPLIT1);
    {
        int n4 = BATCH * D_IN_PROJ / 4;
        reduce_k<SPLIT1><<<(n4 + 255) / 256, 256>>>(p1, zx, n4);
    }

    // 2) conv shift + conv + silu
    conv_kernel<<<(BATCH * CONV_DIM + 255) / 256, 256>>>(
        conv_state, conv_w, conv_b, conv_out, xbc);

    // 3) state update + gated y
    state_kernel<<<dim3(NHEADS, BATCH), 128>>>(
        ssm_state, dt_bias, A_log, Dp, ssm_out, ybuf);

    // 4) out = y @ out_proj_w^T   (256 x 2048), split-K x8
    gemm_tf32<<<dim3(D_MODEL / 64, BATCH / 64, SPLIT2), 128>>>(
        ybuf, out_proj_w, p2, D_MODEL, D_SSM, D_SSM / SPLIT2);
    {
        int n4 = BATCH * D_MODEL / 4;
        reduce_k<SPLIT2><<<(n4 + 255) / 256, 256>>>(p2, out, n4);
    }
}